// round 4
// baseline (speedup 1.0000x reference)
#include <cuda_runtime.h>

// RoiPoolingConv v4: dedup-quad gather.
//  Phase 1: one thread per 2x2 output quad builds a deduped corner table:
//           up to 16 (offset, float4 weights-for-4-outputs) entries.
//  Phase 2: thread = (quad, c4 lane). Loop over n independent entries:
//           v = img[off + c4]; acc_o += v * w_o. Then 4 coalesced stores.
//  Cuts loads/pixel 4 -> ~3.1 while keeping deep per-thread MLP and flat
//  parallelism (no serial dependence, warp-uniform control).

#define MAXQ 16384            // >= num_rois * (pool/2)^2 = 256*49 = 12544

__device__ int    g_cnt[MAXQ];
__device__ int    g_off[MAXQ * 16];      // offsets in float4 units
__device__ float4 g_w  [MAXQ * 16];      // weight for outputs (aa,ab,ba,bb)

__device__ __forceinline__ void axis_corners(int i, int size, int origin,
                                             float poolf,
                                             int& c0, int& c1, float& f)
{
    // Must match reference fp32 sequence exactly up to the floor:
    // scale = size/pool; s = (i+0.5)*scale - 0.5; clip; floor; frac.
    float sf    = (float)size;
    float scale = __fdiv_rn(sf, poolf);
    float s     = __fsub_rn(__fmul_rn((float)i + 0.5f, scale), 0.5f);
    s = fminf(fmaxf(s, 0.0f), sf - 1.0f);
    int i0 = (int)s;                      // s >= 0: trunc == floor
    int i1 = min(i0 + 1, size - 1);
    f  = s - (float)i0;
    c0 = origin + i0;
    c1 = origin + i1;
}

__global__ void roi_quad_tables(const int* __restrict__ rois,
                                int nquads, int qpool, int pool,
                                int W, int C4)
{
    int q = blockIdx.x * blockDim.x + threadIdx.x;
    if (q >= nquads) return;

    const int qpp = qpool * qpool;
    const int r   = q / qpp;
    const int rem = q - r * qpp;
    const int qy  = rem / qpool;
    const int qx  = rem - qy * qpool;

    const int4 roi = __ldg(((const int4*)rois) + r);
    const float poolf = (float)pool;

    const int pxa = 2 * qx;
    const int pxb = min(2 * qx + 1, pool - 1);
    const int pya = 2 * qy;
    const int pyb = min(2 * qy + 1, pool - 1);
    const bool xb_valid = (2 * qx + 1) < pool;
    const bool yb_valid = (2 * qy + 1) < pool;

    int cols[4]; float fxa, fxb;
    axis_corners(pxa, roi.z, roi.x, poolf, cols[0], cols[1], fxa);
    axis_corners(pxb, roi.z, roi.x, poolf, cols[2], cols[3], fxb);
    int rows[4]; float fya, fyb;
    axis_corners(pya, roi.w, roi.y, poolf, rows[0], rows[1], fya);
    axis_corners(pyb, roi.w, roi.y, poolf, rows[2], rows[3], fyb);

    // cw[l][j]: weight of col l for output col-slot j (a,b)
    float cw[4][2] = {
        {1.0f - fxa, 0.0f}, {fxa, 0.0f},
        {0.0f, xb_valid ? 1.0f - fxb : 0.0f}, {0.0f, xb_valid ? fxb : 0.0f}
    };
    float rw[4][2] = {
        {1.0f - fya, 0.0f}, {fya, 0.0f},
        {0.0f, yb_valid ? 1.0f - fyb : 0.0f}, {0.0f, yb_valid ? fyb : 0.0f}
    };

    int    n = 0;
    int    offs[16];
    float4 ws[16];

    #pragma unroll
    for (int k = 0; k < 4; ++k) {
        #pragma unroll
        for (int l = 0; l < 4; ++l) {
            int off = (rows[k] * W + cols[l]) * C4;
            float4 wv;
            wv.x = rw[k][0] * cw[l][0];   // out (ya, xa)
            wv.y = rw[k][0] * cw[l][1];   // out (ya, xb)
            wv.z = rw[k][1] * cw[l][0];   // out (yb, xa)
            wv.w = rw[k][1] * cw[l][1];   // out (yb, xb)
            if (wv.x == 0.0f && wv.y == 0.0f && wv.z == 0.0f && wv.w == 0.0f)
                continue;
            int j = 0;
            for (; j < n; ++j) {
                if (offs[j] == off) {
                    ws[j].x += wv.x; ws[j].y += wv.y;
                    ws[j].z += wv.z; ws[j].w += wv.w;
                    break;
                }
            }
            if (j == n) { offs[n] = off; ws[n] = wv; ++n; }
        }
    }

    g_cnt[q] = n;
    for (int j = 0; j < n; ++j) {
        g_off[q * 16 + j] = offs[j];
        g_w  [q * 16 + j] = ws[j];
    }
}

__global__ void __launch_bounds__(256)
roi_quad_gather(const float* __restrict__ img,
                float*       __restrict__ out,
                int qpool, int pool, int c4shift)
{
    const int gid = blockIdx.x * blockDim.x + threadIdx.x;
    const int C4  = 1 << c4shift;
    const int q   = gid >> c4shift;
    const int c4  = gid & (C4 - 1);

    const int n = g_cnt[q];                 // warp-uniform
    const int*    eo = &g_off[q * 16];
    const float4* ew = &g_w  [q * 16];
    const float4* img4 = (const float4*)img + c4;

    float4 a0 = {0,0,0,0}, a1 = {0,0,0,0}, a2 = {0,0,0,0}, a3 = {0,0,0,0};

    #pragma unroll 4
    for (int e = 0; e < n; ++e) {
        const int    off = __ldg(eo + e);    // broadcast
        const float4 w   = __ldg(ew + e);    // broadcast
        const float4 v   = __ldg(img4 + off);
        a0.x += v.x * w.x; a0.y += v.y * w.x; a0.z += v.z * w.x; a0.w += v.w * w.x;
        a1.x += v.x * w.y; a1.y += v.y * w.y; a1.z += v.z * w.y; a1.w += v.w * w.y;
        a2.x += v.x * w.z; a2.y += v.y * w.z; a2.z += v.z * w.z; a2.w += v.w * w.z;
        a3.x += v.x * w.w; a3.y += v.y * w.w; a3.z += v.z * w.w; a3.w += v.w * w.w;
    }

    // Store 4 outputs
    const int qpp = qpool * qpool;
    const int r   = q / qpp;
    const int rem = q - r * qpp;
    const int qy  = rem / qpool;
    const int qx  = rem - qy * qpool;
    const int pxa = 2 * qx, pya = 2 * qy;
    const bool xb = (pxa + 1) < pool;
    const bool yb = (pya + 1) < pool;

    float4* out4 = (float4*)out;
    const int base = (r * pool + pya) * pool + pxa;

    out4[(size_t)base * C4 + c4] = a0;
    if (xb)       out4[(size_t)(base + 1)        * C4 + c4] = a1;
    if (yb)       out4[(size_t)(base + pool)     * C4 + c4] = a2;
    if (xb && yb) out4[(size_t)(base + pool + 1) * C4 + c4] = a3;
}

extern "C" void kernel_launch(void* const* d_in, const int* in_sizes, int n_in,
                              void* d_out, int out_size)
{
    const float* img  = (const float*)d_in[0];
    const int*   rois = (const int*)d_in[1];
    float*       out  = (float*)d_out;

    const int H = 128, W = 128;
    const int C        = in_sizes[0] / (H * W);      // 512
    const int num_rois = in_sizes[1] / 4;            // 256

    const int pp = out_size / (num_rois * C);
    int pool = 1;
    while (pool * pool < pp) pool++;                 // 14

    const int qpool  = (pool + 1) / 2;               // 7
    const int nquads = num_rois * qpool * qpool;     // 12544

    const int C4 = C >> 2;                           // 128 (power of two)
    int c4shift = 0;
    while ((1 << c4shift) < C4) c4shift++;

    roi_quad_tables<<<(nquads + 127) / 128, 128>>>(
        rois, nquads, qpool, pool, W, C4);

    const int n_threads = nquads * C4;               // 1.6M
    roi_quad_gather<<<(n_threads + 255) / 256, 256>>>(
        img, out, qpool, pool, c4shift);
}

// round 5
// speedup vs baseline: 1.8692x; 1.8692x over previous
#include <cuda_runtime.h>

// RoiPoolingConv v5: R2 flat gather + 2x ILP per thread.
//   Phase 1: per-pixel corner offsets + bilinear weights (unchanged).
//   Phase 2: thread = (pixel, c4 in 0..63) handles chunks c4 and c4+64:
//            1 table load amortized over 8 independent LDG.128 + 2 STG.128.
//            Doubles per-thread MLP, halves broadcast-table wavefronts.

#define MAXPIX 65536   // >= num_rois * pool^2 (256*196 = 50176)

__device__ int4   g_offs[MAXPIX];   // corner offsets in float4 units
__device__ float4 g_wgts[MAXPIX];   // w00, w01, w10, w11

__global__ void roi_precompute_kernel(const int* __restrict__ rois,
                                      int total_pix, int pool,
                                      int W, int C)
{
    int pix = blockIdx.x * blockDim.x + threadIdx.x;
    if (pix >= total_pix) return;

    const int pp = pool * pool;
    const int r  = pix / pp;
    const int rem = pix - r * pp;
    const int py = rem / pool;
    const int px = rem - py * pool;

    const int4 roi = __ldg(((const int4*)rois) + r);
    const int rx = roi.x, ry = roi.y, rw = roi.z, rh = roi.w;

    const float poolf = (float)pool;

    // y axis — fp32 ops must match reference bit-for-bit up to the floor
    float hf     = (float)rh;
    float scaley = __fdiv_rn(hf, poolf);
    float sy     = __fsub_rn(__fmul_rn((float)py + 0.5f, scaley), 0.5f);
    sy = fminf(fmaxf(sy, 0.0f), hf - 1.0f);
    int   iy0 = (int)sy;
    int   iy1 = min(iy0 + 1, rh - 1);
    float fy  = sy - (float)iy0;

    // x axis
    float wf     = (float)rw;
    float scalex = __fdiv_rn(wf, poolf);
    float sx     = __fsub_rn(__fmul_rn((float)px + 0.5f, scalex), 0.5f);
    sx = fminf(fmaxf(sx, 0.0f), wf - 1.0f);
    int   ix0 = (int)sx;
    int   ix1 = min(ix0 + 1, rw - 1);
    float fx  = sx - (float)ix0;

    const int y0 = ry + iy0, y1 = ry + iy1;
    const int x0 = rx + ix0, x1 = rx + ix1;
    const int C4 = C >> 2;

    int4 offs;
    offs.x = (y0 * W + x0) * C4;
    offs.y = (y0 * W + x1) * C4;
    offs.z = (y1 * W + x0) * C4;
    offs.w = (y1 * W + x1) * C4;

    const float gx = 1.0f - fx;
    const float gy = 1.0f - fy;
    float4 w;
    w.x = gx * gy;   // 00
    w.y = fx * gy;   // 01
    w.z = gx * fy;   // 10
    w.w = fx * fy;   // 11

    g_offs[pix] = offs;
    g_wgts[pix] = w;
}

__device__ __forceinline__ float4 blend(float4 a, float4 b, float4 d, float4 e,
                                        float4 w)
{
    float4 res;
    res.x = a.x * w.x + b.x * w.y + d.x * w.z + e.x * w.w;
    res.y = a.y * w.x + b.y * w.y + d.y * w.z + e.y * w.w;
    res.z = a.z * w.x + b.z * w.y + d.z * w.z + e.z * w.w;
    res.w = a.w * w.x + b.w * w.y + d.w * w.z + e.w * w.w;
    return res;
}

__global__ void __launch_bounds__(256)
roi_gather_kernel(const float* __restrict__ img,
                  float*       __restrict__ out,
                  int n_threads)
{
    int gid = blockIdx.x * blockDim.x + threadIdx.x;
    if (gid >= n_threads) return;

    const int pix = gid >> 6;           // 64 threads per pixel
    const int c4  = gid & 63;           // chunk pair: c4 and c4+64

    const int4   offs = g_offs[pix];    // warp-uniform -> broadcast
    const float4 w    = g_wgts[pix];

    const float4* img4 = (const float4*)img;

    // 8 independent loads, issued back-to-back
    float4 a0 = __ldg(img4 + offs.x + c4);
    float4 b0 = __ldg(img4 + offs.y + c4);
    float4 d0 = __ldg(img4 + offs.z + c4);
    float4 e0 = __ldg(img4 + offs.w + c4);
    float4 a1 = __ldg(img4 + offs.x + c4 + 64);
    float4 b1 = __ldg(img4 + offs.y + c4 + 64);
    float4 d1 = __ldg(img4 + offs.z + c4 + 64);
    float4 e1 = __ldg(img4 + offs.w + c4 + 64);

    float4 r0 = blend(a0, b0, d0, e0, w);
    float4 r1 = blend(a1, b1, d1, e1, w);

    float4* o = (float4*)out + ((size_t)pix << 7) + c4;   // C4 = 128
    o[0]  = r0;
    o[64] = r1;
}

extern "C" void kernel_launch(void* const* d_in, const int* in_sizes, int n_in,
                              void* d_out, int out_size)
{
    const float* img  = (const float*)d_in[0];
    const int*   rois = (const int*)d_in[1];
    float*       out  = (float*)d_out;

    const int H = 128, W = 128;
    const int C        = in_sizes[0] / (H * W);      // 512
    const int num_rois = in_sizes[1] / 4;            // 256

    const int pp = out_size / (num_rois * C);
    int pool = 1;
    while (pool * pool < pp) pool++;                 // 14

    const int total_pix = num_rois * pool * pool;    // 50176

    roi_precompute_kernel<<<(total_pix + 255) / 256, 256>>>(
        rois, total_pix, pool, W, C);

    const int n_threads = total_pix * 64;            // 3.21M
    roi_gather_kernel<<<(n_threads + 255) / 256, 256>>>(img, out, n_threads);
}

// round 6
// speedup vs baseline: 1.9776x; 1.0580x over previous
#include <cuda_runtime.h>

// RoiPoolingConv v6: deep-MLP gather + streaming stores.
//   Phase 1: per-pixel corner offsets + bilinear weights (unchanged).
//   Phase 2: warp = one pixel (32 lanes), each thread does 4 channel chunks:
//            1 warp-uniform table load -> 16 independent LDG.128 -> 4 STG.128
//            (streaming, evict-first: keep 33MB image L2-resident against
//            103MB of write traffic).

#define MAXPIX 65536   // >= num_rois * pool^2 (256*196 = 50176)

__device__ int4   g_offs[MAXPIX];   // corner offsets in float4 units
__device__ float4 g_wgts[MAXPIX];   // w00, w01, w10, w11

__global__ void roi_precompute_kernel(const int* __restrict__ rois,
                                      int total_pix, int pool,
                                      int W, int C)
{
    int pix = blockIdx.x * blockDim.x + threadIdx.x;
    if (pix >= total_pix) return;

    const int pp = pool * pool;
    const int r  = pix / pp;
    const int rem = pix - r * pp;
    const int py = rem / pool;
    const int px = rem - py * pool;

    const int4 roi = __ldg(((const int4*)rois) + r);
    const int rx = roi.x, ry = roi.y, rw = roi.z, rh = roi.w;

    const float poolf = (float)pool;

    // y axis — fp32 ops must match reference bit-for-bit up to the floor
    float hf     = (float)rh;
    float scaley = __fdiv_rn(hf, poolf);
    float sy     = __fsub_rn(__fmul_rn((float)py + 0.5f, scaley), 0.5f);
    sy = fminf(fmaxf(sy, 0.0f), hf - 1.0f);
    int   iy0 = (int)sy;
    int   iy1 = min(iy0 + 1, rh - 1);
    float fy  = sy - (float)iy0;

    // x axis
    float wf     = (float)rw;
    float scalex = __fdiv_rn(wf, poolf);
    float sx     = __fsub_rn(__fmul_rn((float)px + 0.5f, scalex), 0.5f);
    sx = fminf(fmaxf(sx, 0.0f), wf - 1.0f);
    int   ix0 = (int)sx;
    int   ix1 = min(ix0 + 1, rw - 1);
    float fx  = sx - (float)ix0;

    const int y0 = ry + iy0, y1 = ry + iy1;
    const int x0 = rx + ix0, x1 = rx + ix1;
    const int C4 = C >> 2;

    int4 offs;
    offs.x = (y0 * W + x0) * C4;
    offs.y = (y0 * W + x1) * C4;
    offs.z = (y1 * W + x0) * C4;
    offs.w = (y1 * W + x1) * C4;

    const float gx = 1.0f - fx;
    const float gy = 1.0f - fy;
    float4 w;
    w.x = gx * gy;   // 00
    w.y = fx * gy;   // 01
    w.z = gx * fy;   // 10
    w.w = fx * fy;   // 11

    g_offs[pix] = offs;
    g_wgts[pix] = w;
}

__device__ __forceinline__ float4 blend(float4 a, float4 b, float4 d, float4 e,
                                        float4 w)
{
    float4 res;
    res.x = a.x * w.x + b.x * w.y + d.x * w.z + e.x * w.w;
    res.y = a.y * w.x + b.y * w.y + d.y * w.z + e.y * w.w;
    res.z = a.z * w.x + b.z * w.y + d.z * w.z + e.z * w.w;
    res.w = a.w * w.x + b.w * w.y + d.w * w.z + e.w * w.w;
    return res;
}

__global__ void __launch_bounds__(256)
roi_gather_kernel(const float* __restrict__ img,
                  float*       __restrict__ out,
                  int n_threads)
{
    int gid = blockIdx.x * blockDim.x + threadIdx.x;
    if (gid >= n_threads) return;

    const int pix = gid >> 5;           // warp = one pixel
    const int c4  = gid & 31;           // chunks c4, +32, +64, +96

    const int4   offs = g_offs[pix];    // warp-uniform -> broadcast
    const float4 w    = g_wgts[pix];

    const float4* img4 = (const float4*)img;
    const float4* pa = img4 + offs.x + c4;
    const float4* pb = img4 + offs.y + c4;
    const float4* pd = img4 + offs.z + c4;
    const float4* pe = img4 + offs.w + c4;

    // 16 independent loads
    float4 a0 = __ldg(pa);       float4 b0 = __ldg(pb);
    float4 d0 = __ldg(pd);       float4 e0 = __ldg(pe);
    float4 a1 = __ldg(pa + 32);  float4 b1 = __ldg(pb + 32);
    float4 d1 = __ldg(pd + 32);  float4 e1 = __ldg(pe + 32);
    float4 a2 = __ldg(pa + 64);  float4 b2 = __ldg(pb + 64);
    float4 d2 = __ldg(pd + 64);  float4 e2 = __ldg(pe + 64);
    float4 a3 = __ldg(pa + 96);  float4 b3 = __ldg(pb + 96);
    float4 d3 = __ldg(pd + 96);  float4 e3 = __ldg(pe + 96);

    float4 r0 = blend(a0, b0, d0, e0, w);
    float4 r1 = blend(a1, b1, d1, e1, w);
    float4 r2 = blend(a2, b2, d2, e2, w);
    float4 r3 = blend(a3, b3, d3, e3, w);

    float4* o = (float4*)out + ((size_t)pix << 7) + c4;   // C4 = 128
    __stcs(o,      r0);     // streaming: evict-first, keep image in L2
    __stcs(o + 32, r1);
    __stcs(o + 64, r2);
    __stcs(o + 96, r3);
}

extern "C" void kernel_launch(void* const* d_in, const int* in_sizes, int n_in,
                              void* d_out, int out_size)
{
    const float* img  = (const float*)d_in[0];
    const int*   rois = (const int*)d_in[1];
    float*       out  = (float*)d_out;

    const int H = 128, W = 128;
    const int C        = in_sizes[0] / (H * W);      // 512
    const int num_rois = in_sizes[1] / 4;            // 256

    const int pp = out_size / (num_rois * C);
    int pool = 1;
    while (pool * pool < pp) pool++;                 // 14

    const int total_pix = num_rois * pool * pool;    // 50176

    roi_precompute_kernel<<<(total_pix + 255) / 256, 256>>>(
        rois, total_pix, pool, W, C);

    const int n_threads = total_pix * 32;            // 1.6M
    roi_gather_kernel<<<(n_threads + 255) / 256, 256>>>(img, out, n_threads);
}

// round 7
// speedup vs baseline: 2.1316x; 1.0779x over previous
#include <cuda_runtime.h>

// RoiPoolingConv v7: fully fused single kernel.
//   grid = (ceil(pool^2 / 8), num_rois), block = 256 (8 warps).
//   Warp = one output pixel. Coordinates computed per-warp in uniform ALU
//   (no precompute kernel, no table round-trip). Each lane handles 4 channel
//   chunks: 16 independent LDG.128 -> 4 blends -> 4 streaming STG.128.

__device__ __forceinline__ float4 blend(float4 a, float4 b, float4 d, float4 e,
                                        float w00, float w01, float w10, float w11)
{
    float4 res;
    res.x = a.x * w00 + b.x * w01 + d.x * w10 + e.x * w11;
    res.y = a.y * w00 + b.y * w01 + d.y * w10 + e.y * w11;
    res.z = a.z * w00 + b.z * w01 + d.z * w10 + e.z * w11;
    res.w = a.w * w00 + b.w * w01 + d.w * w10 + e.w * w11;
    return res;
}

__global__ void __launch_bounds__(256)
roi_fused_kernel(const float* __restrict__ img,
                 const int*   __restrict__ rois,
                 float*       __restrict__ out,
                 int pool, int pp, unsigned magic, int W, int C4)
{
    const int r   = blockIdx.y;
    const int pir = blockIdx.x * 8 + (threadIdx.x >> 5);   // pixel in roi
    if (pir >= pp) return;
    const int c4  = threadIdx.x & 31;                      // chunks +0,32,64,96

    // ROI load first (4KB table -> L1-hot broadcast)
    const int4 roi = __ldg(((const int4*)rois) + r);

    // pir < pool^2 <= 4096: exact magic division by pool via 2^22
    const int py = (int)(((unsigned long long)pir * magic) >> 22);
    const int px = pir - py * pool;

    const float poolf = (float)pool;

    // y axis — fp32 sequence must match reference exactly up to the floor
    float hf     = (float)roi.w;
    float scaley = __fdiv_rn(hf, poolf);
    float sy     = __fsub_rn(__fmul_rn((float)py + 0.5f, scaley), 0.5f);
    sy = fminf(fmaxf(sy, 0.0f), hf - 1.0f);
    int   iy0 = (int)sy;
    int   iy1 = min(iy0 + 1, roi.w - 1);
    float fy  = sy - (float)iy0;

    // x axis
    float wf     = (float)roi.z;
    float scalex = __fdiv_rn(wf, poolf);
    float sx     = __fsub_rn(__fmul_rn((float)px + 0.5f, scalex), 0.5f);
    sx = fminf(fmaxf(sx, 0.0f), wf - 1.0f);
    int   ix0 = (int)sx;
    int   ix1 = min(ix0 + 1, roi.z - 1);
    float fx  = sx - (float)ix0;

    const int y0 = roi.y + iy0, y1 = roi.y + iy1;
    const int x0 = roi.x + ix0, x1 = roi.x + ix1;

    const float gx = 1.0f - fx, gy = 1.0f - fy;
    const float w00 = gx * gy, w01 = fx * gy;
    const float w10 = gx * fy, w11 = fx * fy;

    const float4* img4 = (const float4*)img;
    const float4* pa = img4 + (y0 * W + x0) * C4 + c4;
    const float4* pb = img4 + (y0 * W + x1) * C4 + c4;
    const float4* pd = img4 + (y1 * W + x0) * C4 + c4;
    const float4* pe = img4 + (y1 * W + x1) * C4 + c4;

    // 16 independent loads
    float4 a0 = __ldg(pa);       float4 b0 = __ldg(pb);
    float4 d0 = __ldg(pd);       float4 e0 = __ldg(pe);
    float4 a1 = __ldg(pa + 32);  float4 b1 = __ldg(pb + 32);
    float4 d1 = __ldg(pd + 32);  float4 e1 = __ldg(pe + 32);
    float4 a2 = __ldg(pa + 64);  float4 b2 = __ldg(pb + 64);
    float4 d2 = __ldg(pd + 64);  float4 e2 = __ldg(pe + 64);
    float4 a3 = __ldg(pa + 96);  float4 b3 = __ldg(pb + 96);
    float4 d3 = __ldg(pd + 96);  float4 e3 = __ldg(pe + 96);

    float4 r0 = blend(a0, b0, d0, e0, w00, w01, w10, w11);
    float4 r1 = blend(a1, b1, d1, e1, w00, w01, w10, w11);
    float4 r2 = blend(a2, b2, d2, e2, w00, w01, w10, w11);
    float4 r3 = blend(a3, b3, d3, e3, w00, w01, w10, w11);

    float4* o = (float4*)out + ((size_t)(r * pp + pir)) * C4 + c4;
    __stcs(o,      r0);     // streaming: keep image L2-resident
    __stcs(o + 32, r1);
    __stcs(o + 64, r2);
    __stcs(o + 96, r3);
}

extern "C" void kernel_launch(void* const* d_in, const int* in_sizes, int n_in,
                              void* d_out, int out_size)
{
    const float* img  = (const float*)d_in[0];
    const int*   rois = (const int*)d_in[1];
    float*       out  = (float*)d_out;

    const int H = 128, W = 128;
    const int C        = in_sizes[0] / (H * W);      // 512
    const int num_rois = in_sizes[1] / 4;            // 256

    const int pp = out_size / (num_rois * C);        // pool^2 = 196
    int pool = 1;
    while (pool * pool < pp) pool++;                 // 14

    // magic for exact n/pool, n < 4096: m = ceil(2^22 / pool)
    unsigned magic = (unsigned)((4194304u + pool - 1) / pool);

    dim3 grid((pp + 7) / 8, num_rois);
    roi_fused_kernel<<<grid, 256>>>(img, rois, out, pool, pp, magic, W, C >> 2);
}

// round 8
// speedup vs baseline: 2.1433x; 1.0055x over previous
#include <cuda_runtime.h>
#include <cstdint>

// RoiPoolingConv v8: fused kernel + packed f32x2 datapath.
//   grid = (ceil(pool^2/4), num_rois), block = 128 (4 warps), warp = pixel.
//   Lane handles 4 channel chunks: 16 independent 128-bit loads ->
//   32 packed FFMA2 -> 4 streaming 128-bit stores. Halves FP issue slots
//   vs scalar FFMA; exact-fit grid removes idle warps.

__device__ __forceinline__ uint64_t pack2(float f) {
    uint64_t r; unsigned u = __float_as_uint(f);
    asm("mov.b64 %0, {%1,%1};" : "=l"(r) : "r"(u));
    return r;
}
__device__ __forceinline__ uint64_t fma2(uint64_t a, uint64_t b, uint64_t c) {
    uint64_t r;
    asm("fma.rn.f32x2 %0, %1, %2, %3;" : "=l"(r) : "l"(a), "l"(b), "l"(c));
    return r;
}
__device__ __forceinline__ uint64_t mul2(uint64_t a, uint64_t b) {
    uint64_t r;
    asm("mul.rn.f32x2 %0, %1, %2;" : "=l"(r) : "l"(a), "l"(b));
    return r;
}

struct V2 { uint64_t lo, hi; };

__device__ __forceinline__ V2 ldg2(const char* p) {
    V2 v;
    asm("ld.global.nc.v2.u64 {%0,%1}, [%2];"
        : "=l"(v.lo), "=l"(v.hi) : "l"(p));
    return v;
}
__device__ __forceinline__ void stcs2(char* p, uint64_t lo, uint64_t hi) {
    asm volatile("st.global.cs.v2.u64 [%0], {%1,%2};"
                 :: "l"(p), "l"(lo), "l"(hi) : "memory");
}

__device__ __forceinline__ void blend2(V2 a, V2 b, V2 d, V2 e,
                                       uint64_t W00, uint64_t W01,
                                       uint64_t W10, uint64_t W11,
                                       uint64_t& rlo, uint64_t& rhi)
{
    rlo = fma2(a.lo, W00, fma2(b.lo, W01, fma2(d.lo, W10, mul2(e.lo, W11))));
    rhi = fma2(a.hi, W00, fma2(b.hi, W01, fma2(d.hi, W10, mul2(e.hi, W11))));
}

__global__ void __launch_bounds__(128, 12)
roi_fused_kernel(const float* __restrict__ img,
                 const int*   __restrict__ rois,
                 float*       __restrict__ out,
                 int pool, int pp, unsigned magic, int W, int C4)
{
    const int r   = blockIdx.y;
    const int pir = blockIdx.x * 4 + (threadIdx.x >> 5);   // pixel in roi
    if (pir >= pp) return;
    const int c4  = threadIdx.x & 31;                      // chunks +0,32,64,96

    const int4 roi = __ldg(((const int4*)rois) + r);

    // pir < 4096: exact magic division by pool via 2^22
    const int py = (int)(((unsigned long long)pir * magic) >> 22);
    const int px = pir - py * pool;

    const float poolf = (float)pool;

    // y axis — fp32 sequence must match reference exactly up to the floor
    float hf     = (float)roi.w;
    float scaley = __fdiv_rn(hf, poolf);
    float sy     = __fsub_rn(__fmul_rn((float)py + 0.5f, scaley), 0.5f);
    sy = fminf(fmaxf(sy, 0.0f), hf - 1.0f);
    int   iy0 = (int)sy;
    int   iy1 = min(iy0 + 1, roi.w - 1);
    float fy  = sy - (float)iy0;

    // x axis
    float wf     = (float)roi.z;
    float scalex = __fdiv_rn(wf, poolf);
    float sx     = __fsub_rn(__fmul_rn((float)px + 0.5f, scalex), 0.5f);
    sx = fminf(fmaxf(sx, 0.0f), wf - 1.0f);
    int   ix0 = (int)sx;
    int   ix1 = min(ix0 + 1, roi.z - 1);
    float fx  = sx - (float)ix0;

    const int y0 = roi.y + iy0, y1 = roi.y + iy1;
    const int x0 = roi.x + ix0, x1 = roi.x + ix1;

    const float gx = 1.0f - fx, gy = 1.0f - fy;
    const uint64_t W00 = pack2(gx * gy), W01 = pack2(fx * gy);
    const uint64_t W10 = pack2(gx * fy), W11 = pack2(fx * fy);

    const char* base = (const char*)img;
    const char* pa = base + ((size_t)((y0 * W + x0) * C4 + c4) << 4);
    const char* pb = base + ((size_t)((y0 * W + x1) * C4 + c4) << 4);
    const char* pd = base + ((size_t)((y1 * W + x0) * C4 + c4) << 4);
    const char* pe = base + ((size_t)((y1 * W + x1) * C4 + c4) << 4);

    // 16 independent 128-bit loads (chunk stride 32 float4 = 512B)
    V2 a0 = ldg2(pa);          V2 b0 = ldg2(pb);
    V2 d0 = ldg2(pd);          V2 e0 = ldg2(pe);
    V2 a1 = ldg2(pa + 512);    V2 b1 = ldg2(pb + 512);
    V2 d1 = ldg2(pd + 512);    V2 e1 = ldg2(pe + 512);
    V2 a2 = ldg2(pa + 1024);   V2 b2 = ldg2(pb + 1024);
    V2 d2 = ldg2(pd + 1024);   V2 e2 = ldg2(pe + 1024);
    V2 a3 = ldg2(pa + 1536);   V2 b3 = ldg2(pb + 1536);
    V2 d3 = ldg2(pd + 1536);   V2 e3 = ldg2(pe + 1536);

    uint64_t r0lo, r0hi, r1lo, r1hi, r2lo, r2hi, r3lo, r3hi;
    blend2(a0, b0, d0, e0, W00, W01, W10, W11, r0lo, r0hi);
    blend2(a1, b1, d1, e1, W00, W01, W10, W11, r1lo, r1hi);
    blend2(a2, b2, d2, e2, W00, W01, W10, W11, r2lo, r2hi);
    blend2(a3, b3, d3, e3, W00, W01, W10, W11, r3lo, r3hi);

    char* o = (char*)out + ((size_t)((r * pp + pir) * C4 + c4) << 4);
    stcs2(o,        r0lo, r0hi);   // streaming: keep image L2-resident
    stcs2(o + 512,  r1lo, r1hi);
    stcs2(o + 1024, r2lo, r2hi);
    stcs2(o + 1536, r3lo, r3hi);
}

extern "C" void kernel_launch(void* const* d_in, const int* in_sizes, int n_in,
                              void* d_out, int out_size)
{
    const float* img  = (const float*)d_in[0];
    const int*   rois = (const int*)d_in[1];
    float*       out  = (float*)d_out;

    const int H = 128, W = 128;
    const int C        = in_sizes[0] / (H * W);      // 512
    const int num_rois = in_sizes[1] / 4;            // 256

    const int pp = out_size / (num_rois * C);        // pool^2 = 196
    int pool = 1;
    while (pool * pool < pp) pool++;                 // 14

    // magic for exact n/pool, n < 4096: m = ceil(2^22 / pool)
    unsigned magic = (unsigned)((4194304u + pool - 1) / pool);

    dim3 grid((pp + 3) / 4, num_rois);               // (49, 256) exact fit
    roi_fused_kernel<<<grid, 128>>>(img, rois, out, pool, pp, magic, W, C >> 2);
}

// round 9
// speedup vs baseline: 2.1648x; 1.0100x over previous
#include <cuda_runtime.h>

// RoiPoolingConv v9: fused kernel, scalar (32-bit) memory path.
//   Hypothesis: LDG.128 pays the within-LDG replay rate (2.07 cyc/wavefront,
//   4 lines/inst); LDG.32 with one 128B line per warp-instruction rides the
//   1.0 cyc/wf cross-LDG rate -> read service time halves at identical
//   wavefront count.
//   grid = (pool^2/4, num_rois), block 128, warp = pixel, lane = channel c;
//   loop over 16 channel groups: 4 scalar loads -> blend -> 1 streaming store.

__global__ void __launch_bounds__(128, 8)
roi_fused_kernel(const float* __restrict__ img,
                 const int*   __restrict__ rois,
                 float*       __restrict__ out,
                 int pool, int pp, unsigned magic, int W, int C)
{
    const int r   = blockIdx.y;
    const int pir = blockIdx.x * 4 + (threadIdx.x >> 5);   // pixel in roi
    if (pir >= pp) return;
    const int c   = threadIdx.x & 31;                      // float channel lane

    const int4 roi = __ldg(((const int4*)rois) + r);

    // pir < 4096: exact magic division by pool via 2^22
    const int py = (int)(((unsigned long long)pir * magic) >> 22);
    const int px = pir - py * pool;

    const float poolf = (float)pool;

    // y axis — fp32 sequence must match reference exactly up to the floor
    float hf     = (float)roi.w;
    float scaley = __fdiv_rn(hf, poolf);
    float sy     = __fsub_rn(__fmul_rn((float)py + 0.5f, scaley), 0.5f);
    sy = fminf(fmaxf(sy, 0.0f), hf - 1.0f);
    int   iy0 = (int)sy;
    int   iy1 = min(iy0 + 1, roi.w - 1);
    float fy  = sy - (float)iy0;

    // x axis
    float wf     = (float)roi.z;
    float scalex = __fdiv_rn(wf, poolf);
    float sx     = __fsub_rn(__fmul_rn((float)px + 0.5f, scalex), 0.5f);
    sx = fminf(fmaxf(sx, 0.0f), wf - 1.0f);
    int   ix0 = (int)sx;
    int   ix1 = min(ix0 + 1, roi.z - 1);
    float fx  = sx - (float)ix0;

    const int y0 = roi.y + iy0, y1 = roi.y + iy1;
    const int x0 = roi.x + ix0, x1 = roi.x + ix1;

    const float gx = 1.0f - fx, gy = 1.0f - fy;
    const float w00 = gx * gy, w01 = fx * gy;
    const float w10 = gx * fy, w11 = fx * fy;

    // Scalar lane pointers: warp covers one 128B line per instruction.
    const float* pa = img + (y0 * W + x0) * C + c;
    const float* pb = img + (y0 * W + x1) * C + c;
    const float* pd = img + (y1 * W + x0) * C + c;
    const float* pe = img + (y1 * W + x1) * C + c;

    float* o = out + (size_t)(r * pp + pir) * C + c;

    // 16 channel groups of 32 floats; full unroll lets ptxas batch loads
    // into deep independent groups.
    #pragma unroll
    for (int g = 0; g < 16; ++g) {
        const int off = g * 32;
        float a = __ldg(pa + off);
        float b = __ldg(pb + off);
        float d = __ldg(pd + off);
        float e = __ldg(pe + off);
        float res = a * w00 + b * w01 + d * w10 + e * w11;
        __stcs(o + off, res);          // streaming: keep image L2-resident
    }
}

extern "C" void kernel_launch(void* const* d_in, const int* in_sizes, int n_in,
                              void* d_out, int out_size)
{
    const float* img  = (const float*)d_in[0];
    const int*   rois = (const int*)d_in[1];
    float*       out  = (float*)d_out;

    const int H = 128, W = 128;
    const int C        = in_sizes[0] / (H * W);      // 512
    const int num_rois = in_sizes[1] / 4;            // 256

    const int pp = out_size / (num_rois * C);        // pool^2 = 196
    int pool = 1;
    while (pool * pool < pp) pool++;                 // 14

    // magic for exact n/pool, n < 4096: m = ceil(2^22 / pool)
    unsigned magic = (unsigned)((4194304u + pool - 1) / pool);

    dim3 grid((pp + 3) / 4, num_rois);               // (49, 256) exact fit
    roi_fused_kernel<<<grid, 128>>>(img, rois, out, pool, pp, magic, W, C);
}